// round 15
// baseline (speedup 1.0000x reference)
#include <cuda_runtime.h>
#include <math.h>

// ---- ANI-1x constants ----
#define RCR 5.2f
#define RCA 3.5f
#define ETA_R 16.0f
#define ETA_A 8.0f
#define PI_F 3.14159265358979323846f
#define AEV_W 384
#define BLK 1024
#define HALF_T 512        // threads per half (build/radial: one atom per half)
#define HWN 16            // warps per half
#define NW 32             // total warps
#define NATMAX 512
#define NBMAX2 256

// Gaussian recurrence over the 4 equally spaced ShfA (0.9,1.55,2.2,2.85; delta=0.65):
// e_a = e0 * r^a * q^(a^2),  r = exp(2*eta*delta*t0), q = exp(-eta*delta^2)
#define QA   0.03404745f      // exp(-8*0.65^2)
#define QA2  0.001159229f     // QA^2
#define TWO_ETA_D 10.4f       // 2*8*0.65

// ShfZ = (2k+1)*pi/16 -> cos/sin are exact constants
__constant__ float c_cz[8]  = { 0.98078528f,  0.83146961f,  0.55557023f,  0.19509032f,
                               -0.19509032f, -0.55557023f, -0.83146961f, -0.98078528f};
__constant__ float c_sz[8]  = { 0.19509032f,  0.55557023f,  0.83146961f,  0.98078528f,
                                0.98078528f,  0.83146961f,  0.55557023f,  0.19509032f};

__global__ __launch_bounds__(BLK, 1)
void aev_kernel(const float* __restrict__ coords, float* __restrict__ out, int n) {
    const int tid  = threadIdx.x;
    const int lane = tid & 31;
    const int wid  = tid >> 5;
    const int half = wid >> 4;            // build/radial: which atom this warp serves
    const int hw   = wid & 15;            // warp index within half
    const int t2   = tid & (HALF_T - 1);  // thread index within half
    const int i    = blockIdx.x * 2 + half;
    const bool active = (i < n);

    __shared__ float4 s_xyz[NATMAX];           // staged coords (shared by both halves)
    __shared__ float4 s_nbr[2][NBMAX2];        // per-atom RCA neighbor (ux,uy,uz,d)
    __shared__ float  s_fcA[2][NBMAX2];        // per-atom fc(RCA)
    __shared__ float2 s_rad[2][NBMAX2];        // per-atom RCR neighbor (d, 0.25*fc_r)
    __shared__ int    s_cntA[2][HWN];
    __shared__ int    s_cntR[2][HWN];
    __shared__ int    s_MA[2], s_MR[2];
    __shared__ float  sm_red[2][HWN * 17];     // radial staging, padded
    __shared__ float  sm_ang[2][NW * 33];      // angular staging (all 32 warps x both atoms)
    __shared__ float  fin[2][48];

    // ---- stage coords once for both atoms ----
    if (tid < n) {
        s_xyz[tid] = make_float4(coords[3 * tid + 0], coords[3 * tid + 1],
                                 coords[3 * tid + 2], 0.f);
    }
    __syncthreads();

    float cix = 0.f, ciy = 0.f, ciz = 0.f;
    if (active) { cix = s_xyz[i].x; ciy = s_xyz[i].y; ciz = s_xyz[i].z; }

    // ---- single build pass: compact BOTH the RCA list and the RCR radial list ----
    bool inA = false, inR = false;
    float dx = 0.f, dy = 0.f, dz = 0.f, d2 = 1.f;
    if (active && t2 < n && t2 != i) {
        float4 P = s_xyz[t2];
        dx = cix - P.x; dy = ciy - P.y; dz = ciz - P.z;
        d2 = dx * dx + dy * dy + dz * dz;
        inR = (d2 <= RCR * RCR);
        inA = (d2 <= RCA * RCA);        // inA implies inR
    }
    unsigned balA = __ballot_sync(0xFFFFFFFFu, inA);
    unsigned balR = __ballot_sync(0xFFFFFFFFu, inR);
    if (lane == 0) { s_cntA[half][hw] = __popc(balA); s_cntR[half][hw] = __popc(balR); }
    __syncthreads();
    if (hw == 0) {   // dual segmented scan: lanes 0-15 scan cntA, lanes 16-31 scan cntR
        int l16 = lane & 15;
        int c = (lane < 16) ? s_cntA[half][l16] : s_cntR[half][l16];
        int s = c;
        #pragma unroll
        for (int o = 1; o < 16; o <<= 1) {
            int t = __shfl_up_sync(0xFFFFFFFFu, s, o, 16);
            if (l16 >= o) s += t;
        }
        if (lane < 16) { s_cntA[half][l16] = s - c; if (l16 == 15) s_MA[half] = s; }
        else           { s_cntR[half][l16] = s - c; if (l16 == 15) s_MR[half] = s; }
    }
    __syncthreads();
    const int MR = s_MR[half];
    if (inR) {
        unsigned lml = (1u << lane) - 1u;
        float d = sqrtf(d2);
        int idxR = s_cntR[half][hw] + __popc(balR & lml);
        float fc025 = 0.25f * (0.5f * __cosf(PI_F * (1.0f / RCR) * d) + 0.5f);
        s_rad[half][idxR] = make_float2(d, fc025);
        if (inA) {
            int idxA = s_cntA[half][hw] + __popc(balA & lml);
            float inv = 1.0f / d;
            s_nbr[half][idxA] = make_float4(dx * inv, dy * inv, dz * inv, d);
            s_fcA[half][idxA] = 0.5f * __cosf(PI_F * (1.0f / RCA) * d) + 0.5f;
        }
    }
    __syncthreads();

    // ---- radial over the compacted RCR list: bin-per-lane, 2 j's per warp-iter ----
    {
        const int h = lane >> 4;
        const float shr = 0.9f + 0.26875f * (float)(lane & 15);
        float racc = 0.f;
        for (int it = 0; it * 2 * HWN < MR; it++) {
            int j = (2 * it + h) * HWN + hw;
            bool v = (j < MR);
            float2 R = s_rad[half][v ? j : 0];
            float t = R.x - shr;
            float e = R.y * __expf(-ETA_R * t * t);
            racc += v ? e : 0.f;
        }
        racc += __shfl_xor_sync(0xFFFFFFFFu, racc, 16);
        if (lane < 16) sm_red[half][hw * 17 + lane] = racc;
    }

    // ---- angular: ALL 32 warps share BOTH atoms' rows (combined snake list),
    //      inner loop unrolled x2 (8 pairs/iter), dual accumulator sets ----
    {
        const int pg = lane >> 3;
        const int z  = lane & 7;
        const float czL = c_cz[z];
        const float szL = c_sz[z];
        const int M0 = s_MA[0];
        const int M1 = s_MA[1];
        const int R0 = (M0 > 1) ? (M0 - 1) : 0;    // rows jj = M0-1 .. 1
        const int R1 = (M1 > 1) ? (M1 - 1) : 0;
        const int RT = R0 + R1;
        float a0 = 0.f, a1 = 0.f, a2 = 0.f, a3 = 0.f;   // atom 0 bins
        float b0 = 0.f, b1 = 0.f, b2 = 0.f, b3 = 0.f;   // atom 1 bins

        for (int r = 0; r * NW < RT; r++) {
            int off = (r & 1) ? (NW - 1 - wid) : wid;
            int v = r * NW + off;
            if (v >= RT) continue;
            int h  = (v < R0) ? 0 : 1;
            int jj = (v < R0) ? (M0 - 1 - v) : (M1 - 1 - (v - R0));
            const float4* nb = s_nbr[h];
            const float*  fl = s_fcA[h];
            float4 J = nb[jj];
            float jfc = fl[jj];
            float t0 = 0.f, t1 = 0.f, t2a = 0.f, t3 = 0.f;

            for (int kb = 0; kb < jj; kb += 8) {
                int k1 = kb + pg;
                int k2 = kb + 4 + pg;
                bool ok1 = (k1 < jj);
                bool ok2 = (k2 < jj);
                int kc1 = ok1 ? k1 : 0;
                int kc2 = ok2 ? k2 : 0;
                float4 K1 = nb[kc1];
                float4 K2 = nb[kc2];
                float g1 = ok1 ? (jfc * fl[kc1]) : 0.f;
                float g2 = ok2 ? (jfc * fl[kc2]) : 0.f;

                // --- pair 1 ---
                float ct1 = 0.95f * (J.x * K1.x + J.y * K1.y + J.z * K1.z);
                float st1 = sqrtf(fmaxf(1.0f - ct1 * ct1, 0.0f));
                float dv1 = 0.5f * (J.w + K1.w);
                float x1 = 0.5f + 0.5f * (ct1 * czL + st1 * szL);
                float x1_2 = x1 * x1, x1_4 = x1_2 * x1_2, x1_8 = x1_4 * x1_4, x1_16 = x1_8 * x1_8;
                g1 *= x1_16 * x1_16;
                float u1 = dv1 - 0.9f;
                float e10 = __expf(-ETA_A * u1 * u1);
                float r1  = __expf(TWO_ETA_D * u1);
                float m11 = r1 * QA;
                float e11 = e10 * m11;
                float m12 = m11 * QA2;
                float e12 = e11 * m12;
                float m13 = m12 * QA2;
                float e13 = e12 * m13;

                // --- pair 2 (independent chain) ---
                float ct2 = 0.95f * (J.x * K2.x + J.y * K2.y + J.z * K2.z);
                float st2 = sqrtf(fmaxf(1.0f - ct2 * ct2, 0.0f));
                float dv2 = 0.5f * (J.w + K2.w);
                float x2 = 0.5f + 0.5f * (ct2 * czL + st2 * szL);
                float x2_2 = x2 * x2, x2_4 = x2_2 * x2_2, x2_8 = x2_4 * x2_4, x2_16 = x2_8 * x2_8;
                g2 *= x2_16 * x2_16;
                float u2 = dv2 - 0.9f;
                float e20 = __expf(-ETA_A * u2 * u2);
                float r2  = __expf(TWO_ETA_D * u2);
                float m21 = r2 * QA;
                float e21 = e20 * m21;
                float m22 = m21 * QA2;
                float e22 = e21 * m22;
                float m23 = m22 * QA2;
                float e23 = e22 * m23;

                t0 += g1 * e10 + g2 * e20;
                t1 += g1 * e11 + g2 * e21;
                t2a += g1 * e12 + g2 * e22;
                t3 += g1 * e13 + g2 * e23;
            }
            if (h == 0) { a0 += t0; a1 += t1; a2 += t2a; a3 += t3; }
            else        { b0 += t0; b1 += t1; b2 += t2a; b3 += t3; }
        }

        // fold the 4 pair-groups; lanes 0-7 then hold bins (a, z=lane); stage both sets
        #define FOLD(v) v += __shfl_xor_sync(0xFFFFFFFFu, v, 8); \
                        v += __shfl_xor_sync(0xFFFFFFFFu, v, 16);
        FOLD(a0) FOLD(a1) FOLD(a2) FOLD(a3)
        FOLD(b0) FOLD(b1) FOLD(b2) FOLD(b3)
        #undef FOLD
        if (lane < 8) {
            sm_ang[0][wid * 33 + 0  + lane] = a0;
            sm_ang[0][wid * 33 + 8  + lane] = a1;
            sm_ang[0][wid * 33 + 16 + lane] = a2;
            sm_ang[0][wid * 33 + 24 + lane] = a3;
            sm_ang[1][wid * 33 + 0  + lane] = b0;
            sm_ang[1][wid * 33 + 8  + lane] = b1;
            sm_ang[1][wid * 33 + 16 + lane] = b2;
            sm_ang[1][wid * 33 + 24 + lane] = b3;
        }
    }
    __syncthreads();

    // ---- cross-warp reductions ----
    {
        // radial: warp (half, hw) reduces bin hw of its half over 16 source warps
        float v = (lane < 16) ? sm_red[half][lane * 17 + hw] : 0.f;
        v += __shfl_xor_sync(0xFFFFFFFFu, v, 1);
        v += __shfl_xor_sync(0xFFFFFFFFu, v, 2);
        v += __shfl_xor_sync(0xFFFFFFFFu, v, 4);
        v += __shfl_xor_sync(0xFFFFFFFFu, v, 8);
        if (lane == 0) fin[half][hw] = v;
    }
    {
        // angular: warp (half, hw) reduces bins hw and hw+16 of atom `half`
        // over all 32 source warps (two sequential 32-lane butterflies)
        #pragma unroll
        for (int rep = 0; rep < 2; rep++) {
            int bin = hw + rep * 16;
            float v = sm_ang[half][lane * 33 + bin];
            v += __shfl_xor_sync(0xFFFFFFFFu, v, 1);
            v += __shfl_xor_sync(0xFFFFFFFFu, v, 2);
            v += __shfl_xor_sync(0xFFFFFFFFu, v, 4);
            v += __shfl_xor_sync(0xFFFFFFFFu, v, 8);
            v += __shfl_xor_sync(0xFFFFFFFFu, v, 16);
            if (lane == 0) fin[half][16 + bin] = v;
        }
    }
    __syncthreads();

    // ---- write the full 384-wide row per atom, zeros in species padding ----
    if (active && t2 < AEV_W) {
        float v = 0.f;
        if (t2 < 16) v = fin[half][t2];
        else if (t2 >= 64 && t2 < 96) v = 2.0f * fin[half][16 + (t2 - 64)];  // ordered = 2*(j<k)
        out[i * AEV_W + t2] = v;
    }
}

extern "C" void kernel_launch(void* const* d_in, const int* in_sizes, int n_in,
                              void* d_out, int out_size) {
    const float* coords = (const float*)d_in[0];
    float* out = (float*)d_out;
    int n = in_sizes[0] / 3;
    int grid = (n + 1) / 2;
    aev_kernel<<<grid, BLK>>>(coords, out, n);
}